// round 16
// baseline (speedup 1.0000x reference)
#include <cuda_runtime.h>
#include <cuda_bf16.h>
#include <cuda_fp16.h>
#include <math.h>

#define MAXN 50000
#define MAXE 1600000
#define SCAN_TILE 256
#define MAXB ((MAXN + SCAN_TILE - 1) / SCAN_TILE)

// ---------------- scratch ----------------------------------------------------
// 128-half rows (256B) live in a chunk-swizzled layout: 16B chunk c of row r is
// stored at chunk position (c ^ (r & 7)). Applied uniformly to g_h16, g_a16 and
// the weight tables so cp.async.bulk staging is conflict-free without padding.
__device__ __align__(16) __half g_h16[MAXN * 128];        // GEMM out (L3: 128B rows)
__device__ __align__(16) __half g_a16[(MAXN + 64) * 128]; // agg out (+64 rows pad for bulk tail)
__device__ __align__(16) __half g_w1t[128 * 128];   // W1^T fp16 [n][k], swizzled
__device__ __align__(16) __half g_w2t[128 * 128];   // W2^T fp16 [n][k], swizzled
__device__ __align__(16) __half g_w3t[64 * 128];    // W3^T fp16 padded, swizzled
__device__ __align__(16) float  g_dinv[MAXN];
__device__ int   g_cnt[MAXN];     // zero at entry (zero-init + re-zeroed by scan_pass3)
__device__ int   g_rowptr[MAXN + 1];
__device__ int   g_cursor[MAXN];
__device__ int   g_srcidx[MAXE];
__device__ int   g_bsum[MAXB];
__device__ int   g_boff[MAXB];

// ---------------- preprocessing: hist + weight transpose (merged) ------------
__global__ void prep_kernel(const int* __restrict__ ei, int ne, int eb,
                            const float* __restrict__ W1,
                            const float* __restrict__ W2,
                            const float* __restrict__ W3) {
    int b = blockIdx.x;
    if (b < eb) {
        int e = b * 256 + threadIdx.x;
        if (e < ne) {
            int d = ei[ne + e];
            atomicAdd(&g_cnt[d], 1);
        }
    } else {
        int i = (b - eb) * 256 + threadIdx.x;  // 0..40959
        if (i < 16384) {
            int nn = i >> 7, k = i & 127;
            int dst = nn * 128 + ((((k >> 3) ^ (nn & 7))) << 3) + (k & 7);
            g_w1t[dst] = __float2half(W1[k * 128 + nn]);
        } else if (i < 32768) {
            int j = i - 16384;
            int nn = j >> 7, k = j & 127;
            int dst = nn * 128 + ((((k >> 3) ^ (nn & 7))) << 3) + (k & 7);
            g_w2t[dst] = __float2half(W2[k * 128 + nn]);
        } else if (i < 40960) {
            int j = i - 32768;
            int nn = j >> 7, k = j & 127;
            int dst = nn * 128 + ((((k >> 3) ^ (nn & 7))) << 3) + (k & 7);
            g_w3t[dst] = (nn < 40) ? __float2half(W3[k * 40 + nn]) : __half(0.f);
        }
    }
}

// pass 1 also computes dinv (fused: reads g_cnt anyway)
__global__ void scan_pass1(int n) {
    __shared__ int sh[SCAN_TILE];
    int t = threadIdx.x;
    int i = blockIdx.x * SCAN_TILE + t;
    int v = (i < n) ? g_cnt[i] : 0;
    if (i < n) g_dinv[i] = rsqrtf((float)(v + 1));  // +1 self-loop
    sh[t] = v;
    __syncthreads();
    for (int off = SCAN_TILE / 2; off > 0; off >>= 1) {
        if (t < off) sh[t] += sh[t + off];
        __syncthreads();
    }
    if (t == 0) g_bsum[blockIdx.x] = sh[0];
}

__global__ void scan_pass2(int nb, int n) {
    __shared__ int sh[SCAN_TILE];
    int t = threadIdx.x;
    int v = (t < nb) ? g_bsum[t] : 0;
    sh[t] = v;
    __syncthreads();
    for (int off = 1; off < SCAN_TILE; off <<= 1) {
        int u = (t >= off) ? sh[t - off] : 0;
        __syncthreads();
        sh[t] += u;
        __syncthreads();
    }
    if (t < nb) g_boff[t] = sh[t] - v;
    if (t == nb - 1) g_rowptr[n] = sh[t];
}

// pass 3 also re-zeroes g_cnt so the next launch/graph replay starts clean
__global__ void scan_pass3(int n) {
    __shared__ int sh[SCAN_TILE];
    int t = threadIdx.x;
    int i = blockIdx.x * SCAN_TILE + t;
    int v = (i < n) ? g_cnt[i] : 0;
    sh[t] = v;
    __syncthreads();
    for (int off = 1; off < SCAN_TILE; off <<= 1) {
        int u = (t >= off) ? sh[t - off] : 0;
        __syncthreads();
        sh[t] += u;
        __syncthreads();
    }
    if (i < n) {
        int excl = g_boff[blockIdx.x] + sh[t] - v;
        g_rowptr[i] = excl;
        g_cursor[i] = excl;
        g_cnt[i] = 0;
    }
}

__global__ void fill_kernel(const int* __restrict__ ei, int ne) {
    int e = blockIdx.x * blockDim.x + threadIdx.x;
    if (e < ne) {
        int s = ei[e];
        int d = ei[ne + e];
        int pos = atomicAdd(&g_cursor[d], 1);
        g_srcidx[pos] = s;
    }
}

// ---------------- HMMA GEMM: h' = (A @ B) * dinv[row], fp16 swizzled out ----
// Tiles staged via cp.async.bulk (A: 16KB row block of g_a16; B: whole weight
// table) -> near-zero LDG issue cost. Smem rows 256B, conflict-free via the
// global chunk swizzle. ASEL 0 = A is fp32 x (LDG + swizzled STS).
__device__ __forceinline__ void mma16816(float* c, const unsigned* a, const unsigned* b) {
    asm volatile(
        "mma.sync.aligned.m16n8k16.row.col.f32.f16.f16.f32 "
        "{%0,%1,%2,%3}, {%4,%5,%6,%7}, {%8,%9}, {%0,%1,%2,%3};"
        : "+f"(c[0]), "+f"(c[1]), "+f"(c[2]), "+f"(c[3])
        : "r"(a[0]), "r"(a[1]), "r"(a[2]), "r"(a[3]), "r"(b[0]), "r"(b[1]));
}

__device__ __forceinline__ unsigned smem_u32(const void* p) {
    return (unsigned)__cvta_generic_to_shared(p);
}

template <int BN, int ASEL, int WSEL>
__global__ void __launch_bounds__(256, 4)
gemm_hmma(const float* __restrict__ Axf, int M, int ldc) {
    constexpr int WARPS_N = BN / 32;           // 4 (BN=128) or 2 (BN=64)
    constexpr int WARPS_M = 8 / WARPS_N;       // 2 or 4
    constexpr int MT = (64 / WARPS_M) / 16;    // 2 or 1
    constexpr int A_BYTES = 64 * 256;          // 16KB
    constexpr int B_BYTES = BN * 256;

    extern __shared__ __align__(16) char smem[];
    char* As = smem;                           // [64 rows][256B], swizzled
    char* Bs = smem + A_BYTES;                 // [BN rows][256B], swizzled
    unsigned long long* mbar = (unsigned long long*)(smem + A_BYTES + B_BYTES);

    const __half* __restrict__ Bt =
        (WSEL == 1) ? (const __half*)g_w1t :
        (WSEL == 2) ? (const __half*)g_w2t : (const __half*)g_w3t;

    int tid = threadIdx.x;
    int rowBase = blockIdx.x * 64;

    if (tid == 0) {
        asm volatile("mbarrier.init.shared.b64 [%0], 1;"
                     :: "r"(smem_u32(mbar)) : "memory");
    }
    __syncthreads();
    if (tid == 0) {
        unsigned tx = (ASEL == 1) ? (A_BYTES + B_BYTES) : B_BYTES;
        asm volatile("mbarrier.arrive.expect_tx.shared.b64 _, [%0], %1;"
                     :: "r"(smem_u32(mbar)), "r"(tx) : "memory");
        if (ASEL == 1) {
            asm volatile(
                "cp.async.bulk.shared::cta.global.mbarrier::complete_tx::bytes "
                "[%0], [%1], %2, [%3];"
                :: "r"(smem_u32(As)), "l"((const char*)g_a16 + (size_t)rowBase * 256),
                   "r"((unsigned)A_BYTES), "r"(smem_u32(mbar)) : "memory");
        }
        asm volatile(
            "cp.async.bulk.shared::cta.global.mbarrier::complete_tx::bytes "
            "[%0], [%1], %2, [%3];"
            :: "r"(smem_u32(Bs)), "l"((const char*)Bt),
               "r"((unsigned)B_BYTES), "r"(smem_u32(mbar)) : "memory");
    }

    if (ASEL == 0) {
        // stage fp32 x tile with inline fp16 conversion + swizzled STS
#pragma unroll
        for (int l = 0; l < 8; l++) {
            int idx = tid + l * 256;
            int r = idx >> 5;          // 0..63
            int c4 = idx & 31;         // float4 index within row
            float4 v = make_float4(0.f, 0.f, 0.f, 0.f);
            int grow = rowBase + r;
            if (grow < M) v = *(const float4*)&Axf[grow * 128 + c4 * 4];
            __half2 h[2];
            h[0] = __floats2half2_rn(v.x, v.y);
            h[1] = __floats2half2_rn(v.z, v.w);
            int off = r * 256 + ((((c4 >> 1) ^ (r & 7))) << 4) + ((c4 & 1) << 3);
            *(uint2*)(As + off) = *(uint2*)h;
        }
    }

    // wait for bulk copies (acquire orders async writes for generic reads)
    {
        unsigned mb = smem_u32(mbar);
        unsigned done;
        asm volatile(
            "{\n\t.reg .pred p;\n\t"
            "mbarrier.try_wait.parity.acquire.cta.shared::cta.b64 p, [%1], 0;\n\t"
            "selp.b32 %0, 1, 0, p;\n\t}"
            : "=r"(done) : "r"(mb) : "memory");
        while (!done) {
            asm volatile(
                "{\n\t.reg .pred p;\n\t"
                "mbarrier.try_wait.parity.acquire.cta.shared::cta.b64 p, [%1], 0, 0x989680;\n\t"
                "selp.b32 %0, 1, 0, p;\n\t}"
                : "=r"(done) : "r"(mb) : "memory");
        }
    }
    __syncthreads();  // also covers ASEL=0 STS visibility

    int wid = tid >> 5, lane = tid & 31;
    int g = lane >> 2, t = lane & 3;
    int wm = (wid / WARPS_N) * (MT * 16);
    int wn = (wid % WARPS_N) * 32;

    float acc[MT][4][4];
#pragma unroll
    for (int mi = 0; mi < MT; mi++)
#pragma unroll
        for (int ni = 0; ni < 4; ni++)
#pragma unroll
            for (int q = 0; q < 4; q++) acc[mi][ni][q] = 0.f;

#pragma unroll
    for (int ks = 0; ks < 8; ks++) {
        // swizzled byte offsets within a row for the two 4B fragment words
        int cc0 = ((((2 * ks) ^ g)) << 4) + 4 * t;
        int cc1 = ((((2 * ks + 1) ^ g)) << 4) + 4 * t;
        unsigned afr[MT][4], bfr[4][2];
#pragma unroll
        for (int mi = 0; mi < MT; mi++) {
            int rA = (wm + mi * 16 + g) * 256;
            afr[mi][0] = *(const unsigned*)(As + rA + cc0);
            afr[mi][1] = *(const unsigned*)(As + rA + 8 * 256 + cc0);
            afr[mi][2] = *(const unsigned*)(As + rA + cc1);
            afr[mi][3] = *(const unsigned*)(As + rA + 8 * 256 + cc1);
        }
#pragma unroll
        for (int ni = 0; ni < 4; ni++) {
            int rB = (wn + ni * 8 + g) * 256;
            bfr[ni][0] = *(const unsigned*)(Bs + rB + cc0);
            bfr[ni][1] = *(const unsigned*)(Bs + rB + cc1);
        }
#pragma unroll
        for (int mi = 0; mi < MT; mi++)
#pragma unroll
            for (int ni = 0; ni < 4; ni++)
                mma16816(acc[mi][ni], afr[mi], bfr[ni]);
    }

    // epilogue: scale rows by dinv, store fp16 to swizzled global layout
    int rowBytes = 2 * ldc;  // 256 (L1/L2) or 128 (L3)
#pragma unroll
    for (int mi = 0; mi < MT; mi++) {
        int r0 = rowBase + wm + mi * 16 + g;
        float s0 = (r0 < M) ? g_dinv[r0] : 0.f;
        float s1 = (r0 + 8 < M) ? g_dinv[r0 + 8] : 0.f;
#pragma unroll
        for (int ni = 0; ni < 4; ni++) {
            int c = wn + ni * 8 + 2 * t;
            int coff = (((c >> 3) ^ g) << 4) + 4 * t;
            if (r0 < M) {
                __half2 h = __floats2half2_rn(acc[mi][ni][0] * s0, acc[mi][ni][1] * s0);
                *(__half2*)((char*)g_h16 + (size_t)r0 * rowBytes + coff) = h;
            }
            if (r0 + 8 < M) {
                __half2 h = __floats2half2_rn(acc[mi][ni][2] * s1, acc[mi][ni][3] * s1);
                *(__half2*)((char*)g_h16 + (size_t)(r0 + 8) * rowBytes + coff) = h;
            }
        }
    }
}

// ---------------- aggregation (F=128), warp/node, pure row sum --------------
__device__ __forceinline__ void cvt8(uint4 r, float* f) {
    __half2* p = (__half2*)&r;
    float2 a = __half22float2(p[0]);
    float2 b = __half22float2(p[1]);
    float2 c = __half22float2(p[2]);
    float2 d = __half22float2(p[3]);
    f[0] = a.x; f[1] = a.y; f[2] = b.x; f[3] = b.y;
    f[4] = c.x; f[5] = c.y; f[6] = d.x; f[7] = d.y;
}

__global__ void agg128_kernel(const float* __restrict__ bias, int n, int do_relu) {
    int gw = (blockIdx.x * blockDim.x + threadIdx.x) >> 5;
    if (gw >= n) return;
    int lane = threadIdx.x & 31;
    int hf = lane >> 4;        // which edge of each pair
    int sub = lane & 15;       // feature chunk (constant per lane)
    const uint4* __restrict__ hv = (const uint4*)g_h16;

    float acc[8];
    {   // self-loop h'[d]: each half adds 0.5x (exact after combine)
        float f[8];
        cvt8(hv[gw * 16 + (sub ^ (gw & 7))], f);
#pragma unroll
        for (int q = 0; q < 8; q++) acc[q] = 0.5f * f[q];
    }

    int beg = g_rowptr[gw];
    int end = g_rowptr[gw + 1];
    int i = beg;
    for (; i + 7 < end; i += 8) {
        int sa = g_srcidx[i + 0 + hf];
        int sb = g_srcidx[i + 2 + hf];
        int sc = g_srcidx[i + 4 + hf];
        int sd = g_srcidx[i + 6 + hf];
        uint4 ra = hv[sa * 16 + (sub ^ (sa & 7))];
        uint4 rb = hv[sb * 16 + (sub ^ (sb & 7))];
        uint4 rc = hv[sc * 16 + (sub ^ (sc & 7))];
        uint4 rd = hv[sd * 16 + (sub ^ (sd & 7))];
        float fa[8], fb[8], fc[8], fd[8];
        cvt8(ra, fa);
        cvt8(rb, fb);
        cvt8(rc, fc);
        cvt8(rd, fd);
#pragma unroll
        for (int q = 0; q < 8; q++) acc[q] += (fa[q] + fb[q]) + (fc[q] + fd[q]);
    }
    for (; i + 1 < end; i += 2) {
        int sa = g_srcidx[i + hf];
        uint4 ra = hv[sa * 16 + (sub ^ (sa & 7))];
        float fa[8];
        cvt8(ra, fa);
#pragma unroll
        for (int q = 0; q < 8; q++) acc[q] += fa[q];
    }
    if (i < end) {
        int s0 = g_srcidx[i];
        float w = hf ? 0.f : 1.f;
        uint4 ra = hv[s0 * 16 + (sub ^ (s0 & 7))];
        float fa[8];
        cvt8(ra, fa);
#pragma unroll
        for (int q = 0; q < 8; q++) acc[q] += w * fa[q];
    }
#pragma unroll
    for (int q = 0; q < 8; q++) acc[q] += __shfl_xor_sync(0xFFFFFFFFu, acc[q], 16);

    float dd = g_dinv[gw];
    float4 b0 = ((const float4*)bias)[sub * 2];
    float4 b1 = ((const float4*)bias)[sub * 2 + 1];
    acc[0] = acc[0] * dd + b0.x; acc[1] = acc[1] * dd + b0.y;
    acc[2] = acc[2] * dd + b0.z; acc[3] = acc[3] * dd + b0.w;
    acc[4] = acc[4] * dd + b1.x; acc[5] = acc[5] * dd + b1.y;
    acc[6] = acc[6] * dd + b1.z; acc[7] = acc[7] * dd + b1.w;
    if (do_relu) {
#pragma unroll
        for (int q = 0; q < 8; q++) acc[q] = fmaxf(acc[q], 0.f);
    }
    if (hf == 0) {
        __half2 o[4];
        o[0] = __floats2half2_rn(acc[0], acc[1]);
        o[1] = __floats2half2_rn(acc[2], acc[3]);
        o[2] = __floats2half2_rn(acc[4], acc[5]);
        o[3] = __floats2half2_rn(acc[6], acc[7]);
        ((uint4*)g_a16)[gw * 16 + (sub ^ (gw & 7))] = *(uint4*)o;
    }
}

// ---------------- layer 3 aggregation (F=40, 128B swizzled rows) + softmax --
__global__ void agg40_softmax_kernel(const float* __restrict__ b3,
                                     float* __restrict__ out, int n) {
    int gw = (blockIdx.x * blockDim.x + threadIdx.x) >> 5;
    if (gw >= n) return;
    int lane = threadIdx.x & 31;
    bool act = lane < 20;
    const __half2* __restrict__ hv = (const __half2*)g_h16;  // 32 half2 per row
    int ch = lane >> 2;   // 16B chunk within 128B row
    int wd = lane & 3;    // half2 within chunk

    float2 acc = make_float2(0.f, 0.f);
    if (act) {
        float2 v = __half22float2(hv[gw * 32 + (((ch ^ (gw & 7))) << 2) + wd]);
        acc.x = v.x;
        acc.y = v.y;
    }
    int beg = g_rowptr[gw];
    int end = g_rowptr[gw + 1];
    int i = beg;
    for (; i + 1 < end; i += 2) {
        int s0 = g_srcidx[i], s1 = g_srcidx[i + 1];
        if (act) {
            float2 v0 = __half22float2(hv[s0 * 32 + (((ch ^ (s0 & 7))) << 2) + wd]);
            float2 v1 = __half22float2(hv[s1 * 32 + (((ch ^ (s1 & 7))) << 2) + wd]);
            acc.x += v0.x + v1.x;
            acc.y += v0.y + v1.y;
        }
    }
    if (i < end) {
        int s = g_srcidx[i];
        if (act) {
            float2 v = __half22float2(hv[s * 32 + (((ch ^ (s & 7))) << 2) + wd]);
            acc.x += v.x;
            acc.y += v.y;
        }
    }
    if (act) {
        float dd = g_dinv[gw];
        acc.x = acc.x * dd + b3[lane * 2];
        acc.y = acc.y * dd + b3[lane * 2 + 1];
    }
    float m = act ? fmaxf(acc.x, acc.y) : -INFINITY;
#pragma unroll
    for (int off = 16; off > 0; off >>= 1) m = fmaxf(m, __shfl_xor_sync(0xFFFFFFFFu, m, off));
    float se = act ? (expf(acc.x - m) + expf(acc.y - m)) : 0.f;
#pragma unroll
    for (int off = 16; off > 0; off >>= 1) se += __shfl_xor_sync(0xFFFFFFFFu, se, off);
    float ls = m + logf(se);
    if (act) {
        out[gw * 40 + lane * 2 + 0] = acc.x - ls;
        out[gw * 40 + lane * 2 + 1] = acc.y - ls;
    }
}

// ---------------- launch -----------------------------------------------------
extern "C" void kernel_launch(void* const* d_in, const int* in_sizes, int n_in,
                              void* d_out, int out_size) {
    const float* x = (const float*)d_in[0];
    const int* ei = (const int*)d_in[1];
    const float* W1 = (const float*)d_in[2];
    const float* b1 = (const float*)d_in[3];
    const float* W2 = (const float*)d_in[4];
    const float* b2 = (const float*)d_in[5];
    const float* W3 = (const float*)d_in[6];
    const float* b3 = (const float*)d_in[7];
    float* out = (float*)d_out;

    const int n = in_sizes[0] / 128;   // 50000
    const int ne = in_sizes[1] / 2;    // 1600000

    int eb = (ne + 255) / 256;
    int wb = (n + 7) / 8;
    int sb = (n + SCAN_TILE - 1) / SCAN_TILE;
    int gb = (n + 63) / 64;

    const int SMEM_L12 = 64 * 256 + 128 * 256 + 16;  // 49168
    const int SMEM_L3  = 64 * 256 + 64 * 256 + 16;   // 32784
    cudaFuncSetAttribute((const void*)gemm_hmma<128, 0, 1>,
                         cudaFuncAttributeMaxDynamicSharedMemorySize, SMEM_L12);
    cudaFuncSetAttribute((const void*)gemm_hmma<128, 1, 2>,
                         cudaFuncAttributeMaxDynamicSharedMemorySize, SMEM_L12);
    cudaFuncSetAttribute((const void*)gemm_hmma<64, 1, 3>,
                         cudaFuncAttributeMaxDynamicSharedMemorySize, SMEM_L3);

    // g_cnt is zero at entry (zero-init on load; scan_pass3 re-zeroes each run)
    prep_kernel<<<eb + 160, 256>>>(ei, ne, eb, W1, W2, W3);  // hist + weight transpose
    scan_pass1<<<sb, SCAN_TILE>>>(n);                        // also computes dinv
    scan_pass2<<<1, SCAN_TILE>>>(sb, n);
    gemm_hmma<128, 0, 1><<<gb, 256, SMEM_L12>>>(x, n, 128);  // profiled slot 4
    scan_pass3<<<sb, SCAN_TILE>>>(n);
    fill_kernel<<<eb, 256>>>(ei, ne);

    // layer 1 aggregation
    agg128_kernel<<<wb, 256>>>(b1, n, 1);
    // layer 2
    gemm_hmma<128, 1, 2><<<gb, 256, SMEM_L12>>>(nullptr, n, 128);
    agg128_kernel<<<wb, 256>>>(b2, n, 1);
    // layer 3
    gemm_hmma<64, 1, 3><<<gb, 256, SMEM_L3>>>(nullptr, n, 64);
    agg40_softmax_kernel<<<wb, 256>>>(b3, out, n);
}

// round 17
// speedup vs baseline: 1.0208x; 1.0208x over previous
#include <cuda_runtime.h>
#include <cuda_bf16.h>
#include <cuda_fp16.h>
#include <math.h>

#define MAXN 50000
#define MAXE 1600000
#define SCAN_TILE 256
#define MAXB ((MAXN + SCAN_TILE - 1) / SCAN_TILE)

// ---------------- scratch ----------------------------------------------------
// 128-half rows (256B) live in a chunk-swizzled layout: 16B chunk c of row r is
// stored at chunk position (c ^ (r & 7)). Applied uniformly to g_h16, g_a16 and
// the weight tables so cp.async.bulk staging is conflict-free without padding.
__device__ __align__(16) __half g_h16[MAXN * 128];        // GEMM out (L3: 128B rows)
__device__ __align__(16) __half g_a16[(MAXN + 64) * 128]; // agg out (+64 rows pad for bulk tail)
__device__ __align__(16) __half g_w1t[128 * 128];   // W1^T fp16 [n][k], swizzled
__device__ __align__(16) __half g_w2t[128 * 128];   // W2^T fp16 [n][k], swizzled
__device__ __align__(16) __half g_w3t[64 * 128];    // W3^T fp16 padded, swizzled
__device__ __align__(16) float  g_dinv[MAXN];
__device__ int   g_cnt[MAXN];     // zero at entry (zero-init + re-zeroed by scan_pass3)
__device__ int   g_rowptr[MAXN + 1];
__device__ int   g_cursor[MAXN];
__device__ int   g_srcidx[MAXE];
__device__ int   g_bsum[MAXB];
__device__ int   g_boff[MAXB];

// ---------------- preprocessing: hist + weight transpose (merged) ------------
__global__ void prep_kernel(const int* __restrict__ ei, int ne, int eb,
                            const float* __restrict__ W1,
                            const float* __restrict__ W2,
                            const float* __restrict__ W3) {
    int b = blockIdx.x;
    if (b < eb) {
        int e = b * 256 + threadIdx.x;
        if (e < ne) {
            int d = ei[ne + e];
            atomicAdd(&g_cnt[d], 1);
        }
    } else {
        int i = (b - eb) * 256 + threadIdx.x;  // 0..40959
        if (i < 16384) {
            int nn = i >> 7, k = i & 127;
            int dst = nn * 128 + ((((k >> 3) ^ (nn & 7))) << 3) + (k & 7);
            g_w1t[dst] = __float2half(W1[k * 128 + nn]);
        } else if (i < 32768) {
            int j = i - 16384;
            int nn = j >> 7, k = j & 127;
            int dst = nn * 128 + ((((k >> 3) ^ (nn & 7))) << 3) + (k & 7);
            g_w2t[dst] = __float2half(W2[k * 128 + nn]);
        } else if (i < 40960) {
            int j = i - 32768;
            int nn = j >> 7, k = j & 127;
            int dst = nn * 128 + ((((k >> 3) ^ (nn & 7))) << 3) + (k & 7);
            g_w3t[dst] = (nn < 40) ? __float2half(W3[k * 40 + nn]) : __half(0.f);
        }
    }
}

// pass 1 also computes dinv (fused: reads g_cnt anyway)
__global__ void scan_pass1(int n) {
    __shared__ int sh[SCAN_TILE];
    int t = threadIdx.x;
    int i = blockIdx.x * SCAN_TILE + t;
    int v = (i < n) ? g_cnt[i] : 0;
    if (i < n) g_dinv[i] = rsqrtf((float)(v + 1));  // +1 self-loop
    sh[t] = v;
    __syncthreads();
    for (int off = SCAN_TILE / 2; off > 0; off >>= 1) {
        if (t < off) sh[t] += sh[t + off];
        __syncthreads();
    }
    if (t == 0) g_bsum[blockIdx.x] = sh[0];
}

__global__ void scan_pass2(int nb, int n) {
    __shared__ int sh[SCAN_TILE];
    int t = threadIdx.x;
    int v = (t < nb) ? g_bsum[t] : 0;
    sh[t] = v;
    __syncthreads();
    for (int off = 1; off < SCAN_TILE; off <<= 1) {
        int u = (t >= off) ? sh[t - off] : 0;
        __syncthreads();
        sh[t] += u;
        __syncthreads();
    }
    if (t < nb) g_boff[t] = sh[t] - v;
    if (t == nb - 1) g_rowptr[n] = sh[t];
}

// pass 3 also re-zeroes g_cnt so the next launch/graph replay starts clean
__global__ void scan_pass3(int n) {
    __shared__ int sh[SCAN_TILE];
    int t = threadIdx.x;
    int i = blockIdx.x * SCAN_TILE + t;
    int v = (i < n) ? g_cnt[i] : 0;
    sh[t] = v;
    __syncthreads();
    for (int off = 1; off < SCAN_TILE; off <<= 1) {
        int u = (t >= off) ? sh[t - off] : 0;
        __syncthreads();
        sh[t] += u;
        __syncthreads();
    }
    if (i < n) {
        int excl = g_boff[blockIdx.x] + sh[t] - v;
        g_rowptr[i] = excl;
        g_cursor[i] = excl;
        g_cnt[i] = 0;
    }
}

__global__ void fill_kernel(const int* __restrict__ ei, int ne) {
    int e = blockIdx.x * blockDim.x + threadIdx.x;
    if (e < ne) {
        int s = ei[e];
        int d = ei[ne + e];
        int pos = atomicAdd(&g_cursor[d], 1);
        g_srcidx[pos] = s;
    }
}

// ---------------- HMMA GEMM: h' = (A @ B) * dinv[row], fp16 swizzled out ----
__device__ __forceinline__ void mma16816(float* c, const unsigned* a, const unsigned* b) {
    asm volatile(
        "mma.sync.aligned.m16n8k16.row.col.f32.f16.f16.f32 "
        "{%0,%1,%2,%3}, {%4,%5,%6,%7}, {%8,%9}, {%0,%1,%2,%3};"
        : "+f"(c[0]), "+f"(c[1]), "+f"(c[2]), "+f"(c[3])
        : "r"(a[0]), "r"(a[1]), "r"(a[2]), "r"(a[3]), "r"(b[0]), "r"(b[1]));
}

__device__ __forceinline__ unsigned smem_u32(const void* p) {
    return (unsigned)__cvta_generic_to_shared(p);
}

template <int BN, int ASEL, int WSEL>
__global__ void __launch_bounds__(256, 4)
gemm_hmma(const float* __restrict__ Axf, int M, int ldc) {
    constexpr int WARPS_N = BN / 32;           // 4 (BN=128) or 2 (BN=64)
    constexpr int WARPS_M = 8 / WARPS_N;       // 2 or 4
    constexpr int MT = (64 / WARPS_M) / 16;    // 2 or 1
    constexpr int A_BYTES = 64 * 256;          // 16KB
    constexpr int B_BYTES = BN * 256;

    extern __shared__ __align__(16) char smem[];
    char* As = smem;                           // [64 rows][256B], swizzled
    char* Bs = smem + A_BYTES;                 // [BN rows][256B], swizzled
    unsigned long long* mbar = (unsigned long long*)(smem + A_BYTES + B_BYTES);

    const __half* __restrict__ Bt =
        (WSEL == 1) ? (const __half*)g_w1t :
        (WSEL == 2) ? (const __half*)g_w2t : (const __half*)g_w3t;

    int tid = threadIdx.x;
    int rowBase = blockIdx.x * 64;

    if (tid == 0) {
        asm volatile("mbarrier.init.shared.b64 [%0], 1;"
                     :: "r"(smem_u32(mbar)) : "memory");
    }
    __syncthreads();
    if (tid == 0) {
        unsigned tx = (ASEL == 1) ? (A_BYTES + B_BYTES) : B_BYTES;
        asm volatile("mbarrier.arrive.expect_tx.shared.b64 _, [%0], %1;"
                     :: "r"(smem_u32(mbar)), "r"(tx) : "memory");
        if (ASEL == 1) {
            asm volatile(
                "cp.async.bulk.shared::cta.global.mbarrier::complete_tx::bytes "
                "[%0], [%1], %2, [%3];"
                :: "r"(smem_u32(As)), "l"((const char*)g_a16 + (size_t)rowBase * 256),
                   "r"((unsigned)A_BYTES), "r"(smem_u32(mbar)) : "memory");
        }
        asm volatile(
            "cp.async.bulk.shared::cta.global.mbarrier::complete_tx::bytes "
            "[%0], [%1], %2, [%3];"
            :: "r"(smem_u32(Bs)), "l"((const char*)Bt),
               "r"((unsigned)B_BYTES), "r"(smem_u32(mbar)) : "memory");
    }

    if (ASEL == 0) {
        // stage fp32 x tile with inline fp16 conversion + swizzled STS
#pragma unroll
        for (int l = 0; l < 8; l++) {
            int idx = tid + l * 256;
            int r = idx >> 5;          // 0..63
            int c4 = idx & 31;         // float4 index within row
            float4 v = make_float4(0.f, 0.f, 0.f, 0.f);
            int grow = rowBase + r;
            if (grow < M) v = *(const float4*)&Axf[grow * 128 + c4 * 4];
            __half2 h[2];
            h[0] = __floats2half2_rn(v.x, v.y);
            h[1] = __floats2half2_rn(v.z, v.w);
            int off = r * 256 + ((((c4 >> 1) ^ (r & 7))) << 4) + ((c4 & 1) << 3);
            *(uint2*)(As + off) = *(uint2*)h;
        }
    }

    // wait for bulk copies (acquire orders async writes for generic reads)
    {
        unsigned mb = smem_u32(mbar);
        unsigned done;
        asm volatile(
            "{\n\t.reg .pred p;\n\t"
            "mbarrier.try_wait.parity.acquire.cta.shared::cta.b64 p, [%1], 0;\n\t"
            "selp.b32 %0, 1, 0, p;\n\t}"
            : "=r"(done) : "r"(mb) : "memory");
        while (!done) {
            asm volatile(
                "{\n\t.reg .pred p;\n\t"
                "mbarrier.try_wait.parity.acquire.cta.shared::cta.b64 p, [%1], 0, 0x989680;\n\t"
                "selp.b32 %0, 1, 0, p;\n\t}"
                : "=r"(done) : "r"(mb) : "memory");
        }
    }
    __syncthreads();  // also covers ASEL=0 STS visibility

    int wid = tid >> 5, lane = tid & 31;
    int g = lane >> 2, t = lane & 3;
    int wm = (wid / WARPS_N) * (MT * 16);
    int wn = (wid % WARPS_N) * 32;

    float acc[MT][4][4];
#pragma unroll
    for (int mi = 0; mi < MT; mi++)
#pragma unroll
        for (int ni = 0; ni < 4; ni++)
#pragma unroll
            for (int q = 0; q < 4; q++) acc[mi][ni][q] = 0.f;

#pragma unroll
    for (int ks = 0; ks < 8; ks++) {
        int cc0 = ((((2 * ks) ^ g)) << 4) + 4 * t;
        int cc1 = ((((2 * ks + 1) ^ g)) << 4) + 4 * t;
        unsigned afr[MT][4], bfr[4][2];
#pragma unroll
        for (int mi = 0; mi < MT; mi++) {
            int rA = (wm + mi * 16 + g) * 256;
            afr[mi][0] = *(const unsigned*)(As + rA + cc0);
            afr[mi][1] = *(const unsigned*)(As + rA + 8 * 256 + cc0);
            afr[mi][2] = *(const unsigned*)(As + rA + cc1);
            afr[mi][3] = *(const unsigned*)(As + rA + 8 * 256 + cc1);
        }
#pragma unroll
        for (int ni = 0; ni < 4; ni++) {
            int rB = (wn + ni * 8 + g) * 256;
            bfr[ni][0] = *(const unsigned*)(Bs + rB + cc0);
            bfr[ni][1] = *(const unsigned*)(Bs + rB + cc1);
        }
#pragma unroll
        for (int mi = 0; mi < MT; mi++)
#pragma unroll
            for (int ni = 0; ni < 4; ni++)
                mma16816(acc[mi][ni], afr[mi], bfr[ni]);
    }

    // epilogue: scale rows by dinv, store fp16 to swizzled global layout
    int rowBytes = 2 * ldc;  // 256 (L1/L2) or 128 (L3)
#pragma unroll
    for (int mi = 0; mi < MT; mi++) {
        int r0 = rowBase + wm + mi * 16 + g;
        float s0 = (r0 < M) ? g_dinv[r0] : 0.f;
        float s1 = (r0 + 8 < M) ? g_dinv[r0 + 8] : 0.f;
#pragma unroll
        for (int ni = 0; ni < 4; ni++) {
            int c = wn + ni * 8 + 2 * t;
            int coff = (((c >> 3) ^ g) << 4) + 4 * t;
            if (r0 < M) {
                __half2 h = __floats2half2_rn(acc[mi][ni][0] * s0, acc[mi][ni][1] * s0);
                *(__half2*)((char*)g_h16 + (size_t)r0 * rowBytes + coff) = h;
            }
            if (r0 + 8 < M) {
                __half2 h = __floats2half2_rn(acc[mi][ni][2] * s1, acc[mi][ni][3] * s1);
                *(__half2*)((char*)g_h16 + (size_t)(r0 + 8) * rowBytes + coff) = h;
            }
        }
    }
}

// ---------------- aggregation (F=128), warp/node, pure row sum --------------
__device__ __forceinline__ void cvt8(uint4 r, float* f) {
    __half2* p = (__half2*)&r;
    float2 a = __half22float2(p[0]);
    float2 b = __half22float2(p[1]);
    float2 c = __half22float2(p[2]);
    float2 d = __half22float2(p[3]);
    f[0] = a.x; f[1] = a.y; f[2] = b.x; f[3] = b.y;
    f[4] = c.x; f[5] = c.y; f[6] = d.x; f[7] = d.y;
}

__global__ void agg128_kernel(const float* __restrict__ bias, int n, int do_relu) {
    int gw = (blockIdx.x * blockDim.x + threadIdx.x) >> 5;
    if (gw >= n) return;
    int lane = threadIdx.x & 31;
    int hf = lane >> 4;        // which edge of each pair
    int sub = lane & 15;       // feature chunk (constant per lane)
    const uint4* __restrict__ hv = (const uint4*)g_h16;

    float acc[8];
    {
        float f[8];
        cvt8(hv[gw * 16 + (sub ^ (gw & 7))], f);
#pragma unroll
        for (int q = 0; q < 8; q++) acc[q] = 0.5f * f[q];
    }

    int beg = g_rowptr[gw];
    int end = g_rowptr[gw + 1];
    int i = beg;
    for (; i + 7 < end; i += 8) {
        int sa = g_srcidx[i + 0 + hf];
        int sb = g_srcidx[i + 2 + hf];
        int sc = g_srcidx[i + 4 + hf];
        int sd = g_srcidx[i + 6 + hf];
        uint4 ra = hv[sa * 16 + (sub ^ (sa & 7))];
        uint4 rb = hv[sb * 16 + (sub ^ (sb & 7))];
        uint4 rc = hv[sc * 16 + (sub ^ (sc & 7))];
        uint4 rd = hv[sd * 16 + (sub ^ (sd & 7))];
        float fa[8], fb[8], fc[8], fd[8];
        cvt8(ra, fa);
        cvt8(rb, fb);
        cvt8(rc, fc);
        cvt8(rd, fd);
#pragma unroll
        for (int q = 0; q < 8; q++) acc[q] += (fa[q] + fb[q]) + (fc[q] + fd[q]);
    }
    for (; i + 1 < end; i += 2) {
        int sa = g_srcidx[i + hf];
        uint4 ra = hv[sa * 16 + (sub ^ (sa & 7))];
        float fa[8];
        cvt8(ra, fa);
#pragma unroll
        for (int q = 0; q < 8; q++) acc[q] += fa[q];
    }
    if (i < end) {
        int s0 = g_srcidx[i];
        float w = hf ? 0.f : 1.f;
        uint4 ra = hv[s0 * 16 + (sub ^ (s0 & 7))];
        float fa[8];
        cvt8(ra, fa);
#pragma unroll
        for (int q = 0; q < 8; q++) acc[q] += w * fa[q];
    }
#pragma unroll
    for (int q = 0; q < 8; q++) acc[q] += __shfl_xor_sync(0xFFFFFFFFu, acc[q], 16);

    float dd = g_dinv[gw];
    float4 b0 = ((const float4*)bias)[sub * 2];
    float4 b1 = ((const float4*)bias)[sub * 2 + 1];
    acc[0] = acc[0] * dd + b0.x; acc[1] = acc[1] * dd + b0.y;
    acc[2] = acc[2] * dd + b0.z; acc[3] = acc[3] * dd + b0.w;
    acc[4] = acc[4] * dd + b1.x; acc[5] = acc[5] * dd + b1.y;
    acc[6] = acc[6] * dd + b1.z; acc[7] = acc[7] * dd + b1.w;
    if (do_relu) {
#pragma unroll
        for (int q = 0; q < 8; q++) acc[q] = fmaxf(acc[q], 0.f);
    }
    if (hf == 0) {
        __half2 o[4];
        o[0] = __floats2half2_rn(acc[0], acc[1]);
        o[1] = __floats2half2_rn(acc[2], acc[3]);
        o[2] = __floats2half2_rn(acc[4], acc[5]);
        o[3] = __floats2half2_rn(acc[6], acc[7]);
        ((uint4*)g_a16)[gw * 16 + (sub ^ (gw & 7))] = *(uint4*)o;
    }
}

// ---------------- layer 3 aggregation (F=40, 128B swizzled rows) + softmax --
__global__ void agg40_softmax_kernel(const float* __restrict__ b3,
                                     float* __restrict__ out, int n) {
    int gw = (blockIdx.x * blockDim.x + threadIdx.x) >> 5;
    if (gw >= n) return;
    int lane = threadIdx.x & 31;
    bool act = lane < 20;
    const __half2* __restrict__ hv = (const __half2*)g_h16;  // 32 half2 per row
    int ch = lane >> 2;   // 16B chunk within 128B row
    int wd = lane & 3;    // half2 within chunk

    float2 acc = make_float2(0.f, 0.f);
    if (act) {
        float2 v = __half22float2(hv[gw * 32 + (((ch ^ (gw & 7))) << 2) + wd]);
        acc.x = v.x;
        acc.y = v.y;
    }
    int beg = g_rowptr[gw];
    int end = g_rowptr[gw + 1];
    int i = beg;
    for (; i + 1 < end; i += 2) {
        int s0 = g_srcidx[i], s1 = g_srcidx[i + 1];
        if (act) {
            float2 v0 = __half22float2(hv[s0 * 32 + (((ch ^ (s0 & 7))) << 2) + wd]);
            float2 v1 = __half22float2(hv[s1 * 32 + (((ch ^ (s1 & 7))) << 2) + wd]);
            acc.x += v0.x + v1.x;
            acc.y += v0.y + v1.y;
        }
    }
    if (i < end) {
        int s = g_srcidx[i];
        if (act) {
            float2 v = __half22float2(hv[s * 32 + (((ch ^ (s & 7))) << 2) + wd]);
            acc.x += v.x;
            acc.y += v.y;
        }
    }
    if (act) {
        float dd = g_dinv[gw];
        acc.x = acc.x * dd + b3[lane * 2];
        acc.y = acc.y * dd + b3[lane * 2 + 1];
    }
    float m = act ? fmaxf(acc.x, acc.y) : -INFINITY;
#pragma unroll
    for (int off = 16; off > 0; off >>= 1) m = fmaxf(m, __shfl_xor_sync(0xFFFFFFFFu, m, off));
    float se = act ? (expf(acc.x - m) + expf(acc.y - m)) : 0.f;
#pragma unroll
    for (int off = 16; off > 0; off >>= 1) se += __shfl_xor_sync(0xFFFFFFFFu, se, off);
    float ls = m + logf(se);
    if (act) {
        out[gw * 40 + lane * 2 + 0] = acc.x - ls;
        out[gw * 40 + lane * 2 + 1] = acc.y - ls;
    }
}

// ---------------- launch -----------------------------------------------------
extern "C" void kernel_launch(void* const* d_in, const int* in_sizes, int n_in,
                              void* d_out, int out_size) {
    const float* x = (const float*)d_in[0];
    const int* ei = (const int*)d_in[1];
    const float* W1 = (const float*)d_in[2];
    const float* b1 = (const float*)d_in[3];
    const float* W2 = (const float*)d_in[4];
    const float* b2 = (const float*)d_in[5];
    const float* W3 = (const float*)d_in[6];
    const float* b3 = (const float*)d_in[7];
    float* out = (float*)d_out;

    const int n = in_sizes[0] / 128;   // 50000
    const int ne = in_sizes[1] / 2;    // 1600000

    int eb = (ne + 255) / 256;
    int wb = (n + 7) / 8;
    int sb = (n + SCAN_TILE - 1) / SCAN_TILE;
    int gb = (n + 63) / 64;

    const int SMEM_L12 = 64 * 256 + 128 * 256 + 16;  // 49168
    const int SMEM_L3  = 64 * 256 + 64 * 256 + 16;   // 32784
    cudaFuncSetAttribute((const void*)gemm_hmma<128, 0, 1>,
                         cudaFuncAttributeMaxDynamicSharedMemorySize, SMEM_L12);
    cudaFuncSetAttribute((const void*)gemm_hmma<128, 1, 2>,
                         cudaFuncAttributeMaxDynamicSharedMemorySize, SMEM_L12);
    cudaFuncSetAttribute((const void*)gemm_hmma<64, 1, 3>,
                         cudaFuncAttributeMaxDynamicSharedMemorySize, SMEM_L3);

    // side stream + fork/join events (fresh each call; graph-capture builds
    // parallel branches from eventRecord/streamWaitEvent edges)
    cudaStream_t s2;
    cudaStreamCreateWithFlags(&s2, cudaStreamNonBlocking);
    cudaEvent_t ev1, ev2;
    cudaEventCreateWithFlags(&ev1, cudaEventDisableTiming);
    cudaEventCreateWithFlags(&ev2, cudaEventDisableTiming);

    // main chain: CSR build. g_cnt is zero at entry.
    prep_kernel<<<eb + 160, 256>>>(ei, ne, eb, W1, W2, W3);  // hist + weight transpose
    scan_pass1<<<sb, SCAN_TILE>>>(n);                        // also computes dinv
    cudaEventRecord(ev1, 0);                                 // dinv + weights ready
    scan_pass2<<<1, SCAN_TILE>>>(sb, n);

    // side chain: gemm1 (needs only dinv, weights, x) overlaps scan2/3 + fill
    cudaStreamWaitEvent(s2, ev1, 0);
    gemm_hmma<128, 0, 1><<<gb, 256, SMEM_L12, s2>>>(x, n, 128);  // 4th launch (profiled)
    cudaEventRecord(ev2, s2);

    scan_pass3<<<sb, SCAN_TILE>>>(n);
    fill_kernel<<<eb, 256>>>(ei, ne);
    cudaStreamWaitEvent(0, ev2, 0);   // join: agg1 needs gemm1 + CSR

    // layer 1 aggregation
    agg128_kernel<<<wb, 256>>>(b1, n, 1);
    // layer 2
    gemm_hmma<128, 1, 2><<<gb, 256, SMEM_L12>>>(nullptr, n, 128);
    agg128_kernel<<<wb, 256>>>(b2, n, 1);
    // layer 3
    gemm_hmma<64, 1, 3><<<gb, 256, SMEM_L3>>>(nullptr, n, 64);
    agg40_softmax_kernel<<<wb, 256>>>(b3, out, n);
}